// round 16
// baseline (speedup 1.0000x reference)
#include <cuda_runtime.h>

#define BATCH 2
#define SEQ   2048
#define NH    8
#define HD    64
#define EMB   512
#define EDIM  16
#define MROWS (BATCH*SEQ)   // 4096
#define LOG2E 1.4426950408889634f

// Scratch (no cudaMalloc allowed)
__device__ float g_q[BATCH*NH*SEQ*HD];
__device__ float g_k[BATCH*NH*SEQ*HD];
__device__ float g_v[BATCH*NH*SEQ*HD];
__device__ float g_ao[MROWS*EMB];
__device__ float  g_thr[EDIM];
__device__ float2 g_seg[NH][EDIM + 1];   // (alpha, beta) PRE-SCALED by log2(e)
__device__ unsigned g_pack[(size_t)BATCH*SEQ*SEQ];

// ---------------------------------------------------------------------------
// tf32 helpers
// ---------------------------------------------------------------------------
__device__ __forceinline__ unsigned f2t(float x) {
    unsigned u;
    asm("cvt.rna.tf32.f32 %0, %1;" : "=r"(u) : "f"(x));
    return u;
}

__device__ __forceinline__ void mma8(float& d0, float& d1, float& d2, float& d3,
                                     unsigned a0, unsigned a1, unsigned a2, unsigned a3,
                                     unsigned b0, unsigned b1)
{
    asm volatile(
        "mma.sync.aligned.m16n8k8.row.col.f32.tf32.tf32.f32 "
        "{%0,%1,%2,%3}, {%4,%5,%6,%7}, {%8,%9}, {%0,%1,%2,%3};"
        : "+f"(d0), "+f"(d1), "+f"(d2), "+f"(d3)
        : "r"(a0), "r"(a1), "r"(a2), "r"(a3), "r"(b0), "r"(b1));
}

// ---------------------------------------------------------------------------
// Prep (parallel): piecewise-linear collapse of the edge MLP.
// ---------------------------------------------------------------------------
__global__ void prep_kernel(
    const float* __restrict__ We1, const float* __restrict__ be1,
    const float* __restrict__ We2, const float* __restrict__ be2,
    const float* __restrict__ ebias)
{
    __shared__ float w1s[EDIM], b1s[EDIM], ts[EDIM];
    __shared__ float w2s[NH * EDIM];
    const int tid = threadIdx.x;

    if (tid < EDIM) { w1s[tid] = We1[tid]; b1s[tid] = be1[tid]; }
    if (tid < NH * EDIM) w2s[tid] = We2[tid];
    __syncthreads();

    if (tid == 0) {
        float t[EDIM];
        for (int e = 0; e < EDIM; e++)
            t[e] = (w1s[e] != 0.f) ? (-b1s[e] / w1s[e]) : 1.0e30f;
        for (int i = 1; i < EDIM; i++) {
            float key = t[i];
            int j = i - 1;
            while (j >= 0 && t[j] > key) { t[j + 1] = t[j]; j--; }
            t[j + 1] = key;
        }
        for (int e = 0; e < EDIM; e++) { ts[e] = t[e]; g_thr[e] = t[e]; }
    }
    __syncthreads();

    if (tid < NH * (EDIM + 1)) {
        const int h = tid / (EDIM + 1);
        const int s = tid % (EDIM + 1);
        float amid;
        if (s == 0)          amid = ts[0] - 1.0f;
        else if (s == EDIM)  amid = ts[EDIM - 1] + 1.0f;
        else                 amid = 0.5f * (ts[s - 1] + ts[s]);
        float alpha = ebias[h];
        float beta  = be2[h];
        for (int e = 0; e < EDIM; e++) {
            if (w1s[e] * amid + b1s[e] > 0.f) {
                const float w2 = w2s[h * EDIM + e];
                alpha += w1s[e] * w2;
                beta  += b1s[e] * w2;
            }
        }
        g_seg[h][s] = make_float2(alpha * LOG2E, beta * LOG2E);
    }
}

// ---------------------------------------------------------------------------
// Pack kernel: adjacency value + segment index in low 5 mantissa bits.
// ---------------------------------------------------------------------------
__global__ __launch_bounds__(256) void pack_kernel(const float* __restrict__ adj)
{
    float thr[EDIM];
    #pragma unroll
    for (int e = 0; e < EDIM; e++) thr[e] = g_thr[e];

    const size_t i4 = (size_t)blockIdx.x * blockDim.x + threadIdx.x;
    float4 a = __ldg((const float4*)adj + i4);
    unsigned s0 = 0, s1 = 0, s2 = 0, s3 = 0;
    #pragma unroll
    for (int e = 0; e < EDIM; e++) {
        s0 += (a.x > thr[e]);
        s1 += (a.y > thr[e]);
        s2 += (a.z > thr[e]);
        s3 += (a.w > thr[e]);
    }
    uint4 r;
    r.x = (__float_as_uint(a.x) & ~31u) | s0;
    r.y = (__float_as_uint(a.y) & ~31u) | s1;
    r.z = (__float_as_uint(a.z) & ~31u) | s2;
    r.w = (__float_as_uint(a.w) & ~31u) | s3;
    *((uint4*)g_pack + i4) = r;
}

// ---------------------------------------------------------------------------
// tf32 GEMM core, 512 threads: C(128x128) = A(Mx512) @ W^T.
// Same proven BK=32 / LDP=36 dataflow as the 256-thread core, but 16 warps
// in a 4m x 4n layout; each warp computes 32x32 = 2 m-frags x 4 n-frags.
// Staging: 4 threads per row, 8 floats (2 float4) per matrix per thread.
// ---------------------------------------------------------------------------
__device__ __forceinline__ void gemm_tf32_core512(
    const float* __restrict__ A, const float* __restrict__ W,
    int m0, int n0, float c[2][4][4])
{
    const int LDP = 36;
    __shared__ float As[128 * 36];
    __shared__ float Ws[128 * 36];

    const int tid = threadIdx.x;
    const int w  = tid >> 5;          // 0..15
    const int ln = tid & 31;
    const int g  = ln >> 2;
    const int tg = ln & 3;
    const int wm = (w & 3) * 32;
    const int wn = (w >> 2) * 32;

    const int srow = tid >> 2;        // 0..127
    const int scol = (tid & 3) * 8;   // 0,8,16,24

    const float* Ap = A + (size_t)(m0 + srow) * EMB + scol;
    const float* Wp = W + (size_t)(n0 + srow) * EMB + scol;

    for (int kt = 0; kt < EMB; kt += 32) {
        float4 av[2], wv[2];
        #pragma unroll
        for (int q = 0; q < 2; q++) {
            av[q] = *(const float4*)(Ap + kt + 4 * q);
            wv[q] = *(const float4*)(Wp + kt + 4 * q);
        }
        __syncthreads();
        #pragma unroll
        for (int q = 0; q < 2; q++) {
            *(uint4*)&As[srow * LDP + scol + 4 * q] =
                make_uint4(f2t(av[q].x), f2t(av[q].y), f2t(av[q].z), f2t(av[q].w));
            *(uint4*)&Ws[srow * LDP + scol + 4 * q] =
                make_uint4(f2t(wv[q].x), f2t(wv[q].y), f2t(wv[q].z), f2t(wv[q].w));
        }
        __syncthreads();

        #pragma unroll
        for (int ks = 0; ks < 4; ks++) {
            const int kb = ks * 8;
            unsigned af[2][4];
            #pragma unroll
            for (int mf = 0; mf < 2; mf++) {
                const int r = wm + 16 * mf + g;
                af[mf][0] = __float_as_uint(As[(r    ) * LDP + kb + tg    ]);
                af[mf][1] = __float_as_uint(As[(r + 8) * LDP + kb + tg    ]);
                af[mf][2] = __float_as_uint(As[(r    ) * LDP + kb + tg + 4]);
                af[mf][3] = __float_as_uint(As[(r + 8) * LDP + kb + tg + 4]);
            }
            #pragma unroll
            for (int nf = 0; nf < 4; nf++) {
                const int nr = wn + 8 * nf + g;
                unsigned b0 = __float_as_uint(Ws[nr * LDP + kb + tg    ]);
                unsigned b1 = __float_as_uint(Ws[nr * LDP + kb + tg + 4]);
                mma8(c[0][nf][0], c[0][nf][1], c[0][nf][2], c[0][nf][3],
                     af[0][0], af[0][1], af[0][2], af[0][3], b0, b1);
                mma8(c[1][nf][0], c[1][nf][1], c[1][nf][2], c[1][nf][3],
                     af[1][0], af[1][1], af[1][2], af[1][3], b0, b1);
            }
        }
    }
}

// ---------------------------------------------------------------------------
// QKV projection (512-thread core), outputs stored as tf32 bit patterns.
// Grid (EMB/128, MROWS/128, 3) = 384 CTAs; occ 3 -> single wave.
// ---------------------------------------------------------------------------
__global__ __launch_bounds__(512, 3) void qkv_kernel(
    const float* __restrict__ x,
    const float* __restrict__ Wq, const float* __restrict__ bq,
    const float* __restrict__ Wk, const float* __restrict__ bk,
    const float* __restrict__ Wv, const float* __restrict__ bv)
{
    const int z = blockIdx.z;
    const float* W    = (z == 0) ? Wq : (z == 1) ? Wk : Wv;
    const float* bias = (z == 0) ? bq : (z == 1) ? bk : bv;
    float* dst        = (z == 0) ? g_q : (z == 1) ? g_k : g_v;

    const int m0 = blockIdx.y * 128;
    const int n0 = blockIdx.x * 128;

    float c[2][4][4];
    #pragma unroll
    for (int mf = 0; mf < 2; mf++)
        #pragma unroll
        for (int nf = 0; nf < 4; nf++)
            #pragma unroll
            for (int q = 0; q < 4; q++) c[mf][nf][q] = 0.f;

    gemm_tf32_core512(x, W, m0, n0, c);

    const int ln = threadIdx.x & 31;
    const int g  = ln >> 2;
    const int tg = ln & 3;
    const int wv5 = threadIdx.x >> 5;
    const int wm = (wv5 & 3) * 32;
    const int wn = (wv5 >> 2) * 32;

    #pragma unroll
    for (int mf = 0; mf < 2; mf++) {
        const int m  = m0 + wm + 16 * mf + g;
        const int b0r = m >> 11;
        const int i0r = m & (SEQ - 1);
        const int b1r = (m + 8) >> 11;
        const int i1r = (m + 8) & (SEQ - 1);
        #pragma unroll
        for (int nf = 0; nf < 4; nf++) {
            const int o = n0 + wn + 8 * nf + 2 * tg;
            const int h = o >> 6;
            const int d = o & (HD - 1);
            const float bx = __ldg(&bias[o]);
            const float by = __ldg(&bias[o + 1]);
            *(uint2*)&dst[(((size_t)(b0r * NH + h) * SEQ + i0r) * HD) + d] =
                make_uint2(f2t(c[mf][nf][0] + bx), f2t(c[mf][nf][1] + by));
            *(uint2*)&dst[(((size_t)(b1r * NH + h) * SEQ + i1r) * HD) + d] =
                make_uint2(f2t(c[mf][nf][2] + bx), f2t(c[mf][nf][3] + by));
        }
    }
}

// ---------------------------------------------------------------------------
// Fused flash attention — R13 VERBATIM (proven 226.9us): exp2-domain online
// softmax. Grid: (NH, SEQ/64, BATCH). Block 128 = 4 warps, j-tile 64.
// Smem: SK 64x68 (K then P), SV 64x72 — conflict-free. 35 KB. 4 CTAs/SM.
// ---------------------------------------------------------------------------
__global__ __launch_bounds__(128, 4) void attn_kernel()
{
    __shared__ float SK[64 * 68];
    __shared__ float SV[64 * 72];

    const int h   = blockIdx.x;
    const int i0  = blockIdx.y * 64;
    const int b   = blockIdx.z;
    const int tid = threadIdx.x;
    const int w   = tid >> 5;
    const int ln  = tid & 31;
    const int g   = ln >> 2;
    const int tg  = ln & 3;
    const int rl  = 16 * w + g;

    const float* qbase = g_q + (size_t)(b * NH + h) * SEQ * HD;
    const float* kbase = g_k + (size_t)(b * NH + h) * SEQ * HD;
    const float* vbase = g_v + (size_t)(b * NH + h) * SEQ * HD;
    const unsigned* pbase = g_pack + (size_t)b * SEQ * SEQ;
    const float2* segp = &g_seg[h][0];

    const float* qp0 = qbase + (size_t)(i0 + rl) * HD + tg;

    float O[8][4];
    #pragma unroll
    for (int nt = 0; nt < 8; nt++)
        #pragma unroll
        for (int c = 0; c < 4; c++) O[nt][c] = 0.f;
    float m0 = -3.0e38f, m1 = -3.0e38f, l0 = 0.f, l1 = 0.f;
    const float scale = 0.125f * LOG2E;

    const int srow = tid >> 4;
    const int sc4  = (tid & 15) << 2;

    for (int jt = 0; jt < SEQ / 64; jt++) {
        const int j0 = jt * 64;
        __syncthreads();

        #pragma unroll
        for (int p = 0; p < 8; p++) {
            const int row = srow + p * 8;
            *(float4*)&SK[row * 68 + sc4] = *(const float4*)&kbase[(size_t)(j0 + row) * HD + sc4];
            *(float4*)&SV[row * 72 + sc4] = *(const float4*)&vbase[(size_t)(j0 + row) * HD + sc4];
        }
        __syncthreads();

        float S[8][4];
        #pragma unroll
        for (int nt = 0; nt < 8; nt++)
            #pragma unroll
            for (int c = 0; c < 4; c++) S[nt][c] = 0.f;

        #pragma unroll
        for (int k0 = 0; k0 < 8; k0++) {
            const unsigned q0 = __float_as_uint(__ldg(qp0 + 8 * k0));
            const unsigned q1 = __float_as_uint(__ldg(qp0 + 8 * HD + 8 * k0));
            const unsigned q2 = __float_as_uint(__ldg(qp0 + 8 * k0 + 4));
            const unsigned q3 = __float_as_uint(__ldg(qp0 + 8 * HD + 8 * k0 + 4));
            #pragma unroll
            for (int nt = 0; nt < 8; nt++) {
                unsigned b0 = __float_as_uint(SK[(8 * nt + g) * 68 + 8 * k0 + tg    ]);
                unsigned b1 = __float_as_uint(SK[(8 * nt + g) * 68 + 8 * k0 + tg + 4]);
                mma8(S[nt][0], S[nt][1], S[nt][2], S[nt][3],
                     q0, q1, q2, q3, b0, b1);
            }
        }
        __syncthreads();

        const unsigned* pL = pbase + (size_t)(i0 + rl    ) * SEQ + j0 + 2 * tg;
        const unsigned* pH = pbase + (size_t)(i0 + rl + 8) * SEQ + j0 + 2 * tg;
        #pragma unroll
        for (int nt = 0; nt < 8; nt++) {
            uint2 uL = __ldg((const uint2*)(pL + 8 * nt));
            uint2 uH = __ldg((const uint2*)(pH + 8 * nt));
            const float2 e0 = __ldg(&segp[uL.x & 31u]);
            const float2 e1 = __ldg(&segp[uL.y & 31u]);
            const float2 e2 = __ldg(&segp[uH.x & 31u]);
            const float2 e3 = __ldg(&segp[uH.y & 31u]);
            const float a0 = __uint_as_float(uL.x & ~31u);
            const float a1 = __uint_as_float(uL.y & ~31u);
            const float a2 = __uint_as_float(uH.x & ~31u);
            const float a3 = __uint_as_float(uH.y & ~31u);
            S[nt][0] = fmaf(S[nt][0], scale, fmaf(a0, e0.x, e0.y));
            S[nt][1] = fmaf(S[nt][1], scale, fmaf(a1, e1.x, e1.y));
            S[nt][2] = fmaf(S[nt][2], scale, fmaf(a2, e2.x, e2.y));
            S[nt][3] = fmaf(S[nt][3], scale, fmaf(a3, e3.x, e3.y));
        }

        float mt0 = -3.0e38f, mt1 = -3.0e38f;
        #pragma unroll
        for (int nt = 0; nt < 8; nt++) {
            mt0 = fmaxf(mt0, fmaxf(S[nt][0], S[nt][1]));
            mt1 = fmaxf(mt1, fmaxf(S[nt][2], S[nt][3]));
        }
        mt0 = fmaxf(mt0, __shfl_xor_sync(0xffffffffu, mt0, 1));
        mt0 = fmaxf(mt0, __shfl_xor_sync(0xffffffffu, mt0, 2));
        mt1 = fmaxf(mt1, __shfl_xor_sync(0xffffffffu, mt1, 1));
        mt1 = fmaxf(mt1, __shfl_xor_sync(0xffffffffu, mt1, 2));

        const float mn0 = fmaxf(m0, mt0);
        const float mn1 = fmaxf(m1, mt1);
        const float cr0 = exp2f(m0 - mn0);
        const float cr1 = exp2f(m1 - mn1);
        m0 = mn0; m1 = mn1;

        float rs0 = 0.f, rs1 = 0.f;
        #pragma unroll
        for (int nt = 0; nt < 8; nt++) {
            S[nt][0] = exp2f(S[nt][0] - mn0);
            S[nt][1] = exp2f(S[nt][1] - mn0);
            S[nt][2] = exp2f(S[nt][2] - mn1);
            S[nt][3] = exp2f(S[nt][3] - mn1);
            rs0 += S[nt][0] + S[nt][1];
            rs1 += S[nt][2] + S[nt][3];
        }
        rs0 += __shfl_xor_sync(0xffffffffu, rs0, 1);
        rs0 += __shfl_xor_sync(0xffffffffu, rs0, 2);
        rs1 += __shfl_xor_sync(0xffffffffu, rs1, 1);
        rs1 += __shfl_xor_sync(0xffffffffu, rs1, 2);
        l0 = l0 * cr0 + rs0;
        l1 = l1 * cr1 + rs1;

        #pragma unroll
        for (int nt = 0; nt < 8; nt++) {
            O[nt][0] *= cr0; O[nt][1] *= cr0;
            O[nt][2] *= cr1; O[nt][3] *= cr1;
        }

        #pragma unroll
        for (int nt = 0; nt < 8; nt++) {
            *(float2*)&SK[(rl    ) * 68 + 8 * nt + 2 * tg] =
                make_float2(__uint_as_float(f2t(S[nt][0])), __uint_as_float(f2t(S[nt][1])));
            *(float2*)&SK[(rl + 8) * 68 + 8 * nt + 2 * tg] =
                make_float2(__uint_as_float(f2t(S[nt][2])), __uint_as_float(f2t(S[nt][3])));
        }
        __syncwarp();

        #pragma unroll
        for (int k0 = 0; k0 < 8; k0++) {
            unsigned pa0 = __float_as_uint(SK[(rl    ) * 68 + 8 * k0 + tg    ]);
            unsigned pa1 = __float_as_uint(SK[(rl + 8) * 68 + 8 * k0 + tg    ]);
            unsigned pa2 = __float_as_uint(SK[(rl    ) * 68 + 8 * k0 + tg + 4]);
            unsigned pa3 = __float_as_uint(SK[(rl + 8) * 68 + 8 * k0 + tg + 4]);
            #pragma unroll
            for (int nt = 0; nt < 8; nt++) {
                unsigned b0 = __float_as_uint(SV[(8 * k0 + tg    ) * 72 + 8 * nt + g]);
                unsigned b1 = __float_as_uint(SV[(8 * k0 + tg + 4) * 72 + 8 * nt + g]);
                mma8(O[nt][0], O[nt][1], O[nt][2], O[nt][3], pa0, pa1, pa2, pa3, b0, b1);
            }
        }
    }

    const float iv0 = 1.f / l0;
    const float iv1 = 1.f / l1;
    float* ob = g_ao + (size_t)(b * SEQ + i0 + rl) * EMB + h * HD;
    #pragma unroll
    for (int nt = 0; nt < 8; nt++) {
        *(float2*)&ob[8 * nt + 2 * tg] = make_float2(O[nt][0] * iv0, O[nt][1] * iv0);
        *(float2*)&ob[(size_t)8 * EMB + 8 * nt + 2 * tg] = make_float2(O[nt][2] * iv1, O[nt][3] * iv1);
    }
}

// ---------------------------------------------------------------------------
// Output projection (512-thread core)
// ---------------------------------------------------------------------------
__global__ __launch_bounds__(512, 3) void oproj_kernel(
    const float* __restrict__ Wo, const float* __restrict__ bo,
    float* __restrict__ out)
{
    const int m0 = blockIdx.y * 128;
    const int n0 = blockIdx.x * 128;

    float c[2][4][4];
    #pragma unroll
    for (int mf = 0; mf < 2; mf++)
        #pragma unroll
        for (int nf = 0; nf < 4; nf++)
            #pragma unroll
            for (int q = 0; q < 4; q++) c[mf][nf][q] = 0.f;

    gemm_tf32_core512(g_ao, Wo, m0, n0, c);

    const int ln = threadIdx.x & 31;
    const int g  = ln >> 2;
    const int tg = ln & 3;
    const int wv5 = threadIdx.x >> 5;
    const int wm = (wv5 & 3) * 32;
    const int wn = (wv5 >> 2) * 32;

    #pragma unroll
    for (int mf = 0; mf < 2; mf++) {
        const int m = m0 + wm + 16 * mf + g;
        #pragma unroll
        for (int nf = 0; nf < 4; nf++) {
            const int o = n0 + wn + 8 * nf + 2 * tg;
            const float bx = __ldg(&bo[o]);
            const float by = __ldg(&bo[o + 1]);
            *(float2*)&out[(size_t)m * EMB + o] =
                make_float2(c[mf][nf][0] + bx, c[mf][nf][1] + by);
            *(float2*)&out[(size_t)(m + 8) * EMB + o] =
                make_float2(c[mf][nf][2] + bx, c[mf][nf][3] + by);
        }
    }
}

// ---------------------------------------------------------------------------
extern "C" void kernel_launch(void* const* d_in, const int* in_sizes, int n_in,
                              void* d_out, int out_size)
{
    const float* x   = (const float*)d_in[0];
    const float* adj = (const float*)d_in[1];
    const float* Wq  = (const float*)d_in[2];
    const float* bq  = (const float*)d_in[3];
    const float* Wk  = (const float*)d_in[4];
    const float* bk  = (const float*)d_in[5];
    const float* Wv  = (const float*)d_in[6];
    const float* bv  = (const float*)d_in[7];
    const float* Wo  = (const float*)d_in[8];
    const float* bo  = (const float*)d_in[9];
    const float* We1 = (const float*)d_in[10];
    const float* be1 = (const float*)d_in[11];
    const float* We2 = (const float*)d_in[12];
    const float* be2 = (const float*)d_in[13];
    const float* eb  = (const float*)d_in[14];
    float* out = (float*)d_out;

    prep_kernel<<<1, 256>>>(We1, be1, We2, be2, eb);
    pack_kernel<<<(BATCH * SEQ * SEQ / 4) / 256, 256>>>(adj);
    qkv_kernel<<<dim3(EMB / 128, MROWS / 128, 3), 512>>>(x, Wq, bq, Wk, bk, Wv, bv);
    attn_kernel<<<dim3(NH, SEQ / 64, BATCH), 128>>>();
    oproj_kernel<<<dim3(EMB / 128, MROWS / 128), 512>>>(Wo, bo, out);
}

// round 17
// speedup vs baseline: 1.4211x; 1.4211x over previous
#include <cuda_runtime.h>

#define BATCH 2
#define SEQ   2048
#define NH    8
#define HD    64
#define EMB   512
#define EDIM  16
#define MROWS (BATCH*SEQ)   // 4096
#define LOG2E 1.4426950408889634f

// Scratch (no cudaMalloc allowed)
__device__ float g_q[BATCH*NH*SEQ*HD];
__device__ float g_k[BATCH*NH*SEQ*HD];
__device__ float g_v[BATCH*NH*SEQ*HD];
__device__ float g_ao[MROWS*EMB];
__device__ float  g_thr[EDIM];
__device__ float2 g_seg[NH][EDIM + 1];   // (alpha, beta) PRE-SCALED by log2(e)
__device__ unsigned g_pack[(size_t)BATCH*SEQ*SEQ];

// ---------------------------------------------------------------------------
// tf32 helpers
// ---------------------------------------------------------------------------
__device__ __forceinline__ unsigned f2t(float x) {
    unsigned u;
    asm("cvt.rna.tf32.f32 %0, %1;" : "=r"(u) : "f"(x));
    return u;
}

__device__ __forceinline__ void mma8(float& d0, float& d1, float& d2, float& d3,
                                     unsigned a0, unsigned a1, unsigned a2, unsigned a3,
                                     unsigned b0, unsigned b1)
{
    asm volatile(
        "mma.sync.aligned.m16n8k8.row.col.f32.tf32.tf32.f32 "
        "{%0,%1,%2,%3}, {%4,%5,%6,%7}, {%8,%9}, {%0,%1,%2,%3};"
        : "+f"(d0), "+f"(d1), "+f"(d2), "+f"(d3)
        : "r"(a0), "r"(a1), "r"(a2), "r"(a3), "r"(b0), "r"(b1));
}

// ---------------------------------------------------------------------------
// Prep (parallel): piecewise-linear collapse of the edge MLP.
// ---------------------------------------------------------------------------
__global__ void prep_kernel(
    const float* __restrict__ We1, const float* __restrict__ be1,
    const float* __restrict__ We2, const float* __restrict__ be2,
    const float* __restrict__ ebias)
{
    __shared__ float w1s[EDIM], b1s[EDIM], ts[EDIM];
    __shared__ float w2s[NH * EDIM];
    const int tid = threadIdx.x;

    if (tid < EDIM) { w1s[tid] = We1[tid]; b1s[tid] = be1[tid]; }
    if (tid < NH * EDIM) w2s[tid] = We2[tid];
    __syncthreads();

    if (tid == 0) {
        float t[EDIM];
        for (int e = 0; e < EDIM; e++)
            t[e] = (w1s[e] != 0.f) ? (-b1s[e] / w1s[e]) : 1.0e30f;
        for (int i = 1; i < EDIM; i++) {
            float key = t[i];
            int j = i - 1;
            while (j >= 0 && t[j] > key) { t[j + 1] = t[j]; j--; }
            t[j + 1] = key;
        }
        for (int e = 0; e < EDIM; e++) { ts[e] = t[e]; g_thr[e] = t[e]; }
    }
    __syncthreads();

    if (tid < NH * (EDIM + 1)) {
        const int h = tid / (EDIM + 1);
        const int s = tid % (EDIM + 1);
        float amid;
        if (s == 0)          amid = ts[0] - 1.0f;
        else if (s == EDIM)  amid = ts[EDIM - 1] + 1.0f;
        else                 amid = 0.5f * (ts[s - 1] + ts[s]);
        float alpha = ebias[h];
        float beta  = be2[h];
        for (int e = 0; e < EDIM; e++) {
            if (w1s[e] * amid + b1s[e] > 0.f) {
                const float w2 = w2s[h * EDIM + e];
                alpha += w1s[e] * w2;
                beta  += b1s[e] * w2;
            }
        }
        g_seg[h][s] = make_float2(alpha * LOG2E, beta * LOG2E);
    }
}

// ---------------------------------------------------------------------------
// Pack kernel: adjacency value + segment index in low 5 mantissa bits.
// ---------------------------------------------------------------------------
__global__ __launch_bounds__(256) void pack_kernel(const float* __restrict__ adj)
{
    float thr[EDIM];
    #pragma unroll
    for (int e = 0; e < EDIM; e++) thr[e] = g_thr[e];

    const size_t i4 = (size_t)blockIdx.x * blockDim.x + threadIdx.x;
    float4 a = __ldg((const float4*)adj + i4);
    unsigned s0 = 0, s1 = 0, s2 = 0, s3 = 0;
    #pragma unroll
    for (int e = 0; e < EDIM; e++) {
        s0 += (a.x > thr[e]);
        s1 += (a.y > thr[e]);
        s2 += (a.z > thr[e]);
        s3 += (a.w > thr[e]);
    }
    uint4 r;
    r.x = (__float_as_uint(a.x) & ~31u) | s0;
    r.y = (__float_as_uint(a.y) & ~31u) | s1;
    r.z = (__float_as_uint(a.z) & ~31u) | s2;
    r.w = (__float_as_uint(a.w) & ~31u) | s3;
    *((uint4*)g_pack + i4) = r;
}

// ---------------------------------------------------------------------------
// tf32 GEMM core (proven, BK=32, LDP=36, 256 thr): C(128x128)=A(Mx512)@W^T.
// ---------------------------------------------------------------------------
__device__ __forceinline__ void gemm_tf32_core(
    const float* __restrict__ A, const float* __restrict__ W,
    int m0, int n0, float c[2][8][4])
{
    const int LDP = 36;
    __shared__ float As[128 * 36];
    __shared__ float Ws[128 * 36];

    const int tid = threadIdx.x;
    const int w  = tid >> 5;
    const int ln = tid & 31;
    const int g  = ln >> 2;
    const int tg = ln & 3;
    const int wm = (w & 3) * 32;
    const int wn = (w >> 2) * 64;

    const int srow = tid >> 1;
    const int scol = (tid & 1) * 16;

    const float* Ap = A + (size_t)(m0 + srow) * EMB + scol;
    const float* Wp = W + (size_t)(n0 + srow) * EMB + scol;

    for (int kt = 0; kt < EMB; kt += 32) {
        float4 av[4], wv[4];
        #pragma unroll
        for (int q = 0; q < 4; q++) {
            av[q] = *(const float4*)(Ap + kt + 4 * q);
            wv[q] = *(const float4*)(Wp + kt + 4 * q);
        }
        __syncthreads();
        #pragma unroll
        for (int q = 0; q < 4; q++) {
            *(uint4*)&As[srow * LDP + scol + 4 * q] =
                make_uint4(f2t(av[q].x), f2t(av[q].y), f2t(av[q].z), f2t(av[q].w));
            *(uint4*)&Ws[srow * LDP + scol + 4 * q] =
                make_uint4(f2t(wv[q].x), f2t(wv[q].y), f2t(wv[q].z), f2t(wv[q].w));
        }
        __syncthreads();

        #pragma unroll
        for (int ks = 0; ks < 4; ks++) {
            const int kb = ks * 8;
            unsigned af[2][4];
            #pragma unroll
            for (int mf = 0; mf < 2; mf++) {
                const int r = wm + 16 * mf + g;
                af[mf][0] = __float_as_uint(As[(r    ) * LDP + kb + tg    ]);
                af[mf][1] = __float_as_uint(As[(r + 8) * LDP + kb + tg    ]);
                af[mf][2] = __float_as_uint(As[(r    ) * LDP + kb + tg + 4]);
                af[mf][3] = __float_as_uint(As[(r + 8) * LDP + kb + tg + 4]);
            }
            #pragma unroll
            for (int nf = 0; nf < 8; nf++) {
                const int nr = wn + 8 * nf + g;
                unsigned b0 = __float_as_uint(Ws[nr * LDP + kb + tg    ]);
                unsigned b1 = __float_as_uint(Ws[nr * LDP + kb + tg + 4]);
                mma8(c[0][nf][0], c[0][nf][1], c[0][nf][2], c[0][nf][3],
                     af[0][0], af[0][1], af[0][2], af[0][3], b0, b1);
                mma8(c[1][nf][0], c[1][nf][1], c[1][nf][2], c[1][nf][3],
                     af[1][0], af[1][1], af[1][2], af[1][3], b0, b1);
            }
        }
    }
}

// ---------------------------------------------------------------------------
// QKV projection (tf32 mma, proven core), outputs stored as tf32 bits.
// ---------------------------------------------------------------------------
__global__ __launch_bounds__(256, 2) void qkv_kernel(
    const float* __restrict__ x,
    const float* __restrict__ Wq, const float* __restrict__ bq,
    const float* __restrict__ Wk, const float* __restrict__ bk,
    const float* __restrict__ Wv, const float* __restrict__ bv)
{
    const int z = blockIdx.z;
    const float* W    = (z == 0) ? Wq : (z == 1) ? Wk : Wv;
    const float* bias = (z == 0) ? bq : (z == 1) ? bk : bv;
    float* dst        = (z == 0) ? g_q : (z == 1) ? g_k : g_v;

    const int m0 = blockIdx.y * 128;
    const int n0 = blockIdx.x * 128;

    float c[2][8][4];
    #pragma unroll
    for (int mf = 0; mf < 2; mf++)
        #pragma unroll
        for (int nf = 0; nf < 8; nf++)
            #pragma unroll
            for (int q = 0; q < 4; q++) c[mf][nf][q] = 0.f;

    gemm_tf32_core(x, W, m0, n0, c);

    const int ln = threadIdx.x & 31;
    const int g  = ln >> 2;
    const int tg = ln & 3;
    const int wm = ((threadIdx.x >> 5) & 3) * 32;
    const int wn = (threadIdx.x >> 7) * 64;

    #pragma unroll
    for (int mf = 0; mf < 2; mf++) {
        const int m  = m0 + wm + 16 * mf + g;
        const int b0r = m >> 11;
        const int i0r = m & (SEQ - 1);
        const int b1r = (m + 8) >> 11;
        const int i1r = (m + 8) & (SEQ - 1);
        #pragma unroll
        for (int nf = 0; nf < 8; nf++) {
            const int o = n0 + wn + 8 * nf + 2 * tg;
            const int h = o >> 6;
            const int d = o & (HD - 1);
            const float bx = __ldg(&bias[o]);
            const float by = __ldg(&bias[o + 1]);
            *(uint2*)&dst[(((size_t)(b0r * NH + h) * SEQ + i0r) * HD) + d] =
                make_uint2(f2t(c[mf][nf][0] + bx), f2t(c[mf][nf][1] + by));
            *(uint2*)&dst[(((size_t)(b1r * NH + h) * SEQ + i1r) * HD) + d] =
                make_uint2(f2t(c[mf][nf][2] + bx), f2t(c[mf][nf][3] + by));
        }
    }
}

// ---------------------------------------------------------------------------
// Fused flash attention — R13 VERBATIM (proven 226.9us): exp2-domain online
// softmax. Grid: (NH, SEQ/64, BATCH). Block 128 = 4 warps, j-tile 64.
// Smem: SK 64x68 (K then P), SV 64x72 — conflict-free. 35 KB. 4 CTAs/SM.
// ---------------------------------------------------------------------------
__global__ __launch_bounds__(128, 4) void attn_kernel()
{
    __shared__ float SK[64 * 68];
    __shared__ float SV[64 * 72];

    const int h   = blockIdx.x;
    const int i0  = blockIdx.y * 64;
    const int b   = blockIdx.z;
    const int tid = threadIdx.x;
    const int w   = tid >> 5;
    const int ln  = tid & 31;
    const int g   = ln >> 2;
    const int tg  = ln & 3;
    const int rl  = 16 * w + g;

    const float* qbase = g_q + (size_t)(b * NH + h) * SEQ * HD;
    const float* kbase = g_k + (size_t)(b * NH + h) * SEQ * HD;
    const float* vbase = g_v + (size_t)(b * NH + h) * SEQ * HD;
    const unsigned* pbase = g_pack + (size_t)b * SEQ * SEQ;
    const float2* segp = &g_seg[h][0];

    const float* qp0 = qbase + (size_t)(i0 + rl) * HD + tg;

    float O[8][4];
    #pragma unroll
    for (int nt = 0; nt < 8; nt++)
        #pragma unroll
        for (int c = 0; c < 4; c++) O[nt][c] = 0.f;
    float m0 = -3.0e38f, m1 = -3.0e38f, l0 = 0.f, l1 = 0.f;
    const float scale = 0.125f * LOG2E;

    const int srow = tid >> 4;
    const int sc4  = (tid & 15) << 2;

    for (int jt = 0; jt < SEQ / 64; jt++) {
        const int j0 = jt * 64;
        __syncthreads();

        #pragma unroll
        for (int p = 0; p < 8; p++) {
            const int row = srow + p * 8;
            *(float4*)&SK[row * 68 + sc4] = *(const float4*)&kbase[(size_t)(j0 + row) * HD + sc4];
            *(float4*)&SV[row * 72 + sc4] = *(const float4*)&vbase[(size_t)(j0 + row) * HD + sc4];
        }
        __syncthreads();

        float S[8][4];
        #pragma unroll
        for (int nt = 0; nt < 8; nt++)
            #pragma unroll
            for (int c = 0; c < 4; c++) S[nt][c] = 0.f;

        #pragma unroll
        for (int k0 = 0; k0 < 8; k0++) {
            const unsigned q0 = __float_as_uint(__ldg(qp0 + 8 * k0));
            const unsigned q1 = __float_as_uint(__ldg(qp0 + 8 * HD + 8 * k0));
            const unsigned q2 = __float_as_uint(__ldg(qp0 + 8 * k0 + 4));
            const unsigned q3 = __float_as_uint(__ldg(qp0 + 8 * HD + 8 * k0 + 4));
            #pragma unroll
            for (int nt = 0; nt < 8; nt++) {
                unsigned b0 = __float_as_uint(SK[(8 * nt + g) * 68 + 8 * k0 + tg    ]);
                unsigned b1 = __float_as_uint(SK[(8 * nt + g) * 68 + 8 * k0 + tg + 4]);
                mma8(S[nt][0], S[nt][1], S[nt][2], S[nt][3],
                     q0, q1, q2, q3, b0, b1);
            }
        }
        __syncthreads();

        const unsigned* pL = pbase + (size_t)(i0 + rl    ) * SEQ + j0 + 2 * tg;
        const unsigned* pH = pbase + (size_t)(i0 + rl + 8) * SEQ + j0 + 2 * tg;
        #pragma unroll
        for (int nt = 0; nt < 8; nt++) {
            uint2 uL = __ldg((const uint2*)(pL + 8 * nt));
            uint2 uH = __ldg((const uint2*)(pH + 8 * nt));
            const float2 e0 = __ldg(&segp[uL.x & 31u]);
            const float2 e1 = __ldg(&segp[uL.y & 31u]);
            const float2 e2 = __ldg(&segp[uH.x & 31u]);
            const float2 e3 = __ldg(&segp[uH.y & 31u]);
            const float a0 = __uint_as_float(uL.x & ~31u);
            const float a1 = __uint_as_float(uL.y & ~31u);
            const float a2 = __uint_as_float(uH.x & ~31u);
            const float a3 = __uint_as_float(uH.y & ~31u);
            S[nt][0] = fmaf(S[nt][0], scale, fmaf(a0, e0.x, e0.y));
            S[nt][1] = fmaf(S[nt][1], scale, fmaf(a1, e1.x, e1.y));
            S[nt][2] = fmaf(S[nt][2], scale, fmaf(a2, e2.x, e2.y));
            S[nt][3] = fmaf(S[nt][3], scale, fmaf(a3, e3.x, e3.y));
        }

        float mt0 = -3.0e38f, mt1 = -3.0e38f;
        #pragma unroll
        for (int nt = 0; nt < 8; nt++) {
            mt0 = fmaxf(mt0, fmaxf(S[nt][0], S[nt][1]));
            mt1 = fmaxf(mt1, fmaxf(S[nt][2], S[nt][3]));
        }
        mt0 = fmaxf(mt0, __shfl_xor_sync(0xffffffffu, mt0, 1));
        mt0 = fmaxf(mt0, __shfl_xor_sync(0xffffffffu, mt0, 2));
        mt1 = fmaxf(mt1, __shfl_xor_sync(0xffffffffu, mt1, 1));
        mt1 = fmaxf(mt1, __shfl_xor_sync(0xffffffffu, mt1, 2));

        const float mn0 = fmaxf(m0, mt0);
        const float mn1 = fmaxf(m1, mt1);
        const float cr0 = exp2f(m0 - mn0);
        const float cr1 = exp2f(m1 - mn1);
        m0 = mn0; m1 = mn1;

        float rs0 = 0.f, rs1 = 0.f;
        #pragma unroll
        for (int nt = 0; nt < 8; nt++) {
            S[nt][0] = exp2f(S[nt][0] - mn0);
            S[nt][1] = exp2f(S[nt][1] - mn0);
            S[nt][2] = exp2f(S[nt][2] - mn1);
            S[nt][3] = exp2f(S[nt][3] - mn1);
            rs0 += S[nt][0] + S[nt][1];
            rs1 += S[nt][2] + S[nt][3];
        }
        rs0 += __shfl_xor_sync(0xffffffffu, rs0, 1);
        rs0 += __shfl_xor_sync(0xffffffffu, rs0, 2);
        rs1 += __shfl_xor_sync(0xffffffffu, rs1, 1);
        rs1 += __shfl_xor_sync(0xffffffffu, rs1, 2);
        l0 = l0 * cr0 + rs0;
        l1 = l1 * cr1 + rs1;

        #pragma unroll
        for (int nt = 0; nt < 8; nt++) {
            O[nt][0] *= cr0; O[nt][1] *= cr0;
            O[nt][2] *= cr1; O[nt][3] *= cr1;
        }

        #pragma unroll
        for (int nt = 0; nt < 8; nt++) {
            *(float2*)&SK[(rl    ) * 68 + 8 * nt + 2 * tg] =
                make_float2(__uint_as_float(f2t(S[nt][0])), __uint_as_float(f2t(S[nt][1])));
            *(float2*)&SK[(rl + 8) * 68 + 8 * nt + 2 * tg] =
                make_float2(__uint_as_float(f2t(S[nt][2])), __uint_as_float(f2t(S[nt][3])));
        }
        __syncwarp();

        #pragma unroll
        for (int k0 = 0; k0 < 8; k0++) {
            unsigned pa0 = __float_as_uint(SK[(rl    ) * 68 + 8 * k0 + tg    ]);
            unsigned pa1 = __float_as_uint(SK[(rl + 8) * 68 + 8 * k0 + tg    ]);
            unsigned pa2 = __float_as_uint(SK[(rl    ) * 68 + 8 * k0 + tg + 4]);
            unsigned pa3 = __float_as_uint(SK[(rl + 8) * 68 + 8 * k0 + tg + 4]);
            #pragma unroll
            for (int nt = 0; nt < 8; nt++) {
                unsigned b0 = __float_as_uint(SV[(8 * k0 + tg    ) * 72 + 8 * nt + g]);
                unsigned b1 = __float_as_uint(SV[(8 * k0 + tg + 4) * 72 + 8 * nt + g]);
                mma8(O[nt][0], O[nt][1], O[nt][2], O[nt][3], pa0, pa1, pa2, pa3, b0, b1);
            }
        }
    }

    const float iv0 = 1.f / l0;
    const float iv1 = 1.f / l1;
    float* ob = g_ao + (size_t)(b * SEQ + i0 + rl) * EMB + h * HD;
    #pragma unroll
    for (int nt = 0; nt < 8; nt++) {
        *(float2*)&ob[8 * nt + 2 * tg] = make_float2(O[nt][0] * iv0, O[nt][1] * iv0);
        *(float2*)&ob[(size_t)8 * EMB + 8 * nt + 2 * tg] = make_float2(O[nt][2] * iv1, O[nt][3] * iv1);
    }
}

// ---------------------------------------------------------------------------
// Output projection (tf32 mma, proven core)
// ---------------------------------------------------------------------------
__global__ __launch_bounds__(256, 2) void oproj_kernel(
    const float* __restrict__ Wo, const float* __restrict__ bo,
    float* __restrict__ out)
{
    const int m0 = blockIdx.y * 128;
    const int n0 = blockIdx.x * 128;

    float c[2][8][4];
    #pragma unroll
    for (int mf = 0; mf < 2; mf++)
        #pragma unroll
        for (int nf = 0; nf < 8; nf++)
            #pragma unroll
            for (int q = 0; q < 4; q++) c[mf][nf][q] = 0.f;

    gemm_tf32_core(g_ao, Wo, m0, n0, c);

    const int ln = threadIdx.x & 31;
    const int g  = ln >> 2;
    const int tg = ln & 3;
    const int wm = ((threadIdx.x >> 5) & 3) * 32;
    const int wn = (threadIdx.x >> 7) * 64;

    #pragma unroll
    for (int mf = 0; mf < 2; mf++) {
        const int m = m0 + wm + 16 * mf + g;
        #pragma unroll
        for (int nf = 0; nf < 8; nf++) {
            const int o = n0 + wn + 8 * nf + 2 * tg;
            const float bx = __ldg(&bo[o]);
            const float by = __ldg(&bo[o + 1]);
            *(float2*)&out[(size_t)m * EMB + o] =
                make_float2(c[mf][nf][0] + bx, c[mf][nf][1] + by);
            *(float2*)&out[(size_t)(m + 8) * EMB + o] =
                make_float2(c[mf][nf][2] + bx, c[mf][nf][3] + by);
        }
    }
}

// ---------------------------------------------------------------------------
// Launch: qkv runs on a side stream concurrently with prep+pack (they are
// data-independent); attn waits on both via event join. Streams/events are
// created once on the first (uncaptured) call — host objects only.
// ---------------------------------------------------------------------------
extern "C" void kernel_launch(void* const* d_in, const int* in_sizes, int n_in,
                              void* d_out, int out_size)
{
    const float* x   = (const float*)d_in[0];
    const float* adj = (const float*)d_in[1];
    const float* Wq  = (const float*)d_in[2];
    const float* bq  = (const float*)d_in[3];
    const float* Wk  = (const float*)d_in[4];
    const float* bk  = (const float*)d_in[5];
    const float* Wv  = (const float*)d_in[6];
    const float* bv  = (const float*)d_in[7];
    const float* Wo  = (const float*)d_in[8];
    const float* bo  = (const float*)d_in[9];
    const float* We1 = (const float*)d_in[10];
    const float* be1 = (const float*)d_in[11];
    const float* We2 = (const float*)d_in[12];
    const float* be2 = (const float*)d_in[13];
    const float* eb  = (const float*)d_in[14];
    float* out = (float*)d_out;

    static cudaStream_t s_side = 0;
    static cudaEvent_t  e_fork = 0, e_join = 0;
    if (s_side == 0) {
        cudaStreamCreateWithFlags(&s_side, cudaStreamNonBlocking);
        cudaEventCreateWithFlags(&e_fork, cudaEventDisableTiming);
        cudaEventCreateWithFlags(&e_join, cudaEventDisableTiming);
    }

    // fork: side stream inherits the capture dependency from stream 0
    cudaEventRecord(e_fork, 0);
    cudaStreamWaitEvent(s_side, e_fork, 0);

    // side stream: qkv (independent of prep/pack)
    qkv_kernel<<<dim3(EMB / 128, MROWS / 128, 3), 256, 0, s_side>>>(
        x, Wq, bq, Wk, bk, Wv, bv);
    cudaEventRecord(e_join, s_side);

    // main stream: edge-MLP prep + adjacency pack (concurrent with qkv)
    prep_kernel<<<1, 256>>>(We1, be1, We2, be2, eb);
    pack_kernel<<<(BATCH * SEQ * SEQ / 4) / 256, 256>>>(adj);

    // join: attn needs q/k/v AND pack/seg tables
    cudaStreamWaitEvent(0, e_join, 0);
    attn_kernel<<<dim3(NH, SEQ / 64, BATCH), 128>>>();
    oproj_kernel<<<dim3(EMB / 128, MROWS / 128), 256>>>(Wo, bo, out);
}